// round 1
// baseline (speedup 1.0000x reference)
#include <cuda_runtime.h>
#include <math.h>

#define Nn 50000
#define Ee 800000
#define ETOT 850000
#define Hh 96
#define Gg 64
#define NCLS 4
#define BNEPS 1e-5f

// ---------------- device scratch (static, no allocs) ----------------
__device__ float g_h[Nn * Hh];      // current node features
__device__ float g_id[Nn * Hh];     // identity (residual)
__device__ float g_hp[Nn * Hh];     // h @ W (per GAT layer)
__device__ float g_tmp[Nn * Hh];    // GAT output before BN
__device__ float g_ss[Nn], g_sd[Nn];
__device__ int   g_deg[Nn];
__device__ int   g_rs[Nn + 1];
__device__ int   g_cur[Nn];
__device__ int   g_csr[ETOT];
__device__ float g_bnsum[Hh], g_bnsq[Hh];
__device__ float g_pooled[Gg * Hh];
__device__ float g_cnt[Gg];

__device__ __forceinline__ float lrelu01(float v) { return v >= 0.f ? v : 0.01f * v; }

// ---------------- zero / init ----------------
__global__ void zero_k() {
    int i = blockIdx.x * blockDim.x + threadIdx.x;
    int stride = gridDim.x * blockDim.x;
    for (int j = i; j < Nn; j += stride) g_deg[j] = 0;
    if (i < Gg * Hh) g_pooled[i] = 0.f;
    if (i < Gg) g_cnt[i] = 0.f;
}

__global__ void zerobn_k() {
    if (threadIdx.x < Hh) { g_bnsum[threadIdx.x] = 0.f; g_bnsq[threadIdx.x] = 0.f; }
}

// ---------------- CSR build ----------------
__global__ void count_k(const int* __restrict__ ei) {
    int i = blockIdx.x * blockDim.x + threadIdx.x;
    if (i >= ETOT) return;
    int d = (i < Ee) ? ei[Ee + i] : (i - Ee);
    atomicAdd(&g_deg[d], 1);
}

__global__ void scan_k() {
    __shared__ int part[1024];
    int t = threadIdx.x;
    const int CH = (Nn + 1023) / 1024;   // 49
    int base = t * CH;
    int s = 0;
    for (int i = 0; i < CH; i++) {
        int idx = base + i;
        if (idx < Nn) s += g_deg[idx];
    }
    part[t] = s;
    __syncthreads();
    // Hillis-Steele inclusive scan
    for (int off = 1; off < 1024; off <<= 1) {
        int v = (t >= off) ? part[t - off] : 0;
        __syncthreads();
        part[t] += v;
        __syncthreads();
    }
    int run = (t == 0) ? 0 : part[t - 1];
    for (int i = 0; i < CH; i++) {
        int idx = base + i;
        if (idx < Nn) {
            g_rs[idx] = run;
            g_cur[idx] = run;
            run += g_deg[idx];
        }
    }
    if (t == blockDim.x - 1) g_rs[Nn] = part[blockDim.x - 1];
}

__global__ void scatter_k(const int* __restrict__ ei) {
    int i = blockIdx.x * blockDim.x + threadIdx.x;
    if (i >= ETOT) return;
    int sN, dN;
    if (i < Ee) { sN = ei[i]; dN = ei[Ee + i]; }
    else        { sN = i - Ee; dN = i - Ee; }
    int pos = atomicAdd(&g_cur[dN], 1);
    g_csr[pos] = sN;
}

// ---------------- GEMM: C[M,96] = act(A[M,K] @ W[K,96] + bias) ----------------
// block: 384 threads; tile 64 rows x 96 cols; micro-tile 4x4
template <int ACT, bool DUP>
__global__ __launch_bounds__(384) void gemm96(
    const float* __restrict__ A, const float* __restrict__ W,
    const float* __restrict__ bias, float* __restrict__ C,
    float* __restrict__ C2, int M, int K)
{
    __shared__ float Ash[32][68];   // transposed A chunk [k][m]
    __shared__ float Wsh[32][96];
    int tid = threadIdx.x;
    int cg = tid % 24;             // col group: cols cg*4 .. +3
    int rg = tid / 24;             // row group: rows rg*4 .. +3
    int rowBase = blockIdx.x * 64;
    float acc[4][4] = {};
    for (int kc = 0; kc < K; kc += 32) {
        for (int idx = tid; idx < 64 * 32; idx += 384) {
            int m = idx >> 5, k = idx & 31;
            int r = rowBase + m;
            Ash[k][m] = (r < M) ? A[r * K + kc + k] : 0.f;
        }
        #pragma unroll
        for (int j = 0; j < 8; j++) {
            int idx = tid + j * 384;
            int k = idx / 96, c = idx % 96;
            Wsh[k][c] = W[(kc + k) * 96 + c];
        }
        __syncthreads();
        #pragma unroll
        for (int k = 0; k < 32; k++) {
            float4 a = *(const float4*)&Ash[k][rg * 4];
            float4 w = *(const float4*)&Wsh[k][cg * 4];
            float av[4] = {a.x, a.y, a.z, a.w};
            float wv[4] = {w.x, w.y, w.z, w.w};
            #pragma unroll
            for (int i = 0; i < 4; i++)
                #pragma unroll
                for (int j = 0; j < 4; j++)
                    acc[i][j] = fmaf(av[i], wv[j], acc[i][j]);
        }
        __syncthreads();
    }
    int c0 = cg * 4;
    float bv[4];
    #pragma unroll
    for (int j = 0; j < 4; j++) bv[j] = bias ? bias[c0 + j] : 0.f;
    #pragma unroll
    for (int i = 0; i < 4; i++) {
        int r = rowBase + rg * 4 + i;
        if (r < M) {
            float4 o;
            float v0 = acc[i][0] + bv[0];
            float v1 = acc[i][1] + bv[1];
            float v2 = acc[i][2] + bv[2];
            float v3 = acc[i][3] + bv[3];
            if (ACT) { v0 = lrelu01(v0); v1 = lrelu01(v1); v2 = lrelu01(v2); v3 = lrelu01(v3); }
            o.x = v0; o.y = v1; o.z = v2; o.w = v3;
            *(float4*)&C[r * 96 + c0] = o;
            if (DUP) *(float4*)&C2[r * 96 + c0] = o;
        }
    }
}

// ---------------- per-node attention scores ----------------
__global__ void scores_k(const float* __restrict__ hp,
                         const float* __restrict__ as_, const float* __restrict__ ad_,
                         float* __restrict__ ss, float* __restrict__ sd)
{
    int w = (blockIdx.x * blockDim.x + threadIdx.x) >> 5;
    int lane = threadIdx.x & 31;
    if (w >= Nn) return;
    const float* row = hp + w * 96;
    float s1 = 0.f, s2 = 0.f;
    #pragma unroll
    for (int j = 0; j < 3; j++) {
        float v = row[lane + 32 * j];
        s1 = fmaf(v, as_[lane + 32 * j], s1);
        s2 = fmaf(v, ad_[lane + 32 * j], s2);
    }
    #pragma unroll
    for (int o = 16; o; o >>= 1) {
        s1 += __shfl_xor_sync(0xffffffffu, s1, o);
        s2 += __shfl_xor_sync(0xffffffffu, s2, o);
    }
    if (lane == 0) { ss[w] = s1; sd[w] = s2; }
}

// ---------------- GAT aggregation: warp per destination node ----------------
__global__ void agg_k(const float* __restrict__ hp,
                      const float* __restrict__ ss, const float* __restrict__ sd,
                      const float* __restrict__ bias, float* __restrict__ out)
{
    int d = (blockIdx.x * blockDim.x + threadIdx.x) >> 5;
    int lane = threadIdx.x & 31;
    if (d >= Nn) return;
    int s0 = g_rs[d], s1e = g_rs[d + 1];
    float sdd = sd[d];
    // pass 1: max
    float m = -3.4e38f;
    for (int j = s0 + lane; j < s1e; j += 32) {
        int s = g_csr[j];
        float e = ss[s] + sdd;
        e = (e >= 0.f) ? e : 0.2f * e;
        m = fmaxf(m, e);
    }
    #pragma unroll
    for (int o = 16; o; o >>= 1) m = fmaxf(m, __shfl_xor_sync(0xffffffffu, m, o));
    // pass 2: denominator
    float denom = 0.f;
    for (int j = s0 + lane; j < s1e; j += 32) {
        int s = g_csr[j];
        float e = ss[s] + sdd;
        e = (e >= 0.f) ? e : 0.2f * e;
        denom += __expf(e - m);
    }
    #pragma unroll
    for (int o = 16; o; o >>= 1) denom += __shfl_xor_sync(0xffffffffu, denom, o);
    float inv = 1.f / denom;
    // pass 3: weighted aggregation (all 32 lanes on features)
    float a0 = 0.f, a1 = 0.f, a2 = 0.f;
    for (int j = s0; j < s1e; j++) {
        int s = g_csr[j];                 // warp-uniform broadcast load
        float e = ss[s] + sdd;
        e = (e >= 0.f) ? e : 0.2f * e;
        float wgt = __expf(e - m) * inv;
        const float* row = hp + s * 96;
        a0 = fmaf(wgt, row[lane], a0);
        a1 = fmaf(wgt, row[lane + 32], a1);
        a2 = fmaf(wgt, row[lane + 64], a2);
    }
    out[d * 96 + lane]      = a0 + bias[lane];
    out[d * 96 + lane + 32] = a1 + bias[lane + 32];
    out[d * 96 + lane + 64] = a2 + bias[lane + 64];
}

// ---------------- BatchNorm ----------------
__global__ void bnstats_k(const float* __restrict__ t) {
    int c = threadIdx.x;   // 96 threads
    float s = 0.f, q = 0.f;
    for (int r = blockIdx.x; r < Nn; r += gridDim.x) {
        float v = t[r * 96 + c];
        s += v;
        q = fmaf(v, v, q);
    }
    atomicAdd(&g_bnsum[c], s);
    atomicAdd(&g_bnsq[c], q);
}

__global__ void bnapply_k(const float* __restrict__ t, const float* __restrict__ idn,
                          const float* __restrict__ gma, const float* __restrict__ bta,
                          float* __restrict__ out)
{
    __shared__ float sc[96], sh[96];
    if (threadIdx.x < 96) {
        int c = threadIdx.x;
        float mu = g_bnsum[c] * (1.f / Nn);
        float var = g_bnsq[c] * (1.f / Nn) - mu * mu;
        float is = rsqrtf(var + BNEPS);
        float gv = gma[c];
        sc[c] = gv * is;
        sh[c] = bta[c] - mu * gv * is;
    }
    __syncthreads();
    int i = blockIdx.x * blockDim.x + threadIdx.x;
    int stride = gridDim.x * blockDim.x;
    for (; i < Nn * 96; i += stride) {
        int c = i % 96;
        float v = fmaf(t[i], sc[c], sh[c]);
        v = lrelu01(v);
        out[i] = v + idn[i];
    }
}

// ---------------- Poincare expmap0 + segment pooling ----------------
__global__ void expool_k(const float* __restrict__ h, const int* __restrict__ batch) {
    __shared__ float sp[Gg * Hh];
    __shared__ float scn[Gg];
    for (int i = threadIdx.x; i < Gg * Hh; i += blockDim.x) sp[i] = 0.f;
    if (threadIdx.x < Gg) scn[threadIdx.x] = 0.f;
    __syncthreads();
    int lane = threadIdx.x & 31;
    int warp = (blockIdx.x * blockDim.x + threadIdx.x) >> 5;
    int nwarps = (gridDim.x * blockDim.x) >> 5;
    for (int n = warp; n < Nn; n += nwarps) {
        float v0 = h[n * 96 + lane];
        float v1 = h[n * 96 + lane + 32];
        float v2 = h[n * 96 + lane + 64];
        float q = v0 * v0 + v1 * v1 + v2 * v2;
        #pragma unroll
        for (int o = 16; o; o >>= 1) q += __shfl_xor_sync(0xffffffffu, q, o);
        float nrm = fmaxf(sqrtf(q), 1e-15f);
        float s = tanhf(nrm) / nrm;
        int g = batch[n];
        atomicAdd(&sp[g * 96 + lane], v0 * s);
        atomicAdd(&sp[g * 96 + lane + 32], v1 * s);
        atomicAdd(&sp[g * 96 + lane + 64], v2 * s);
        if (lane == 0) atomicAdd(&scn[g], 1.f);
    }
    __syncthreads();
    for (int i = threadIdx.x; i < Gg * Hh; i += blockDim.x) atomicAdd(&g_pooled[i], sp[i]);
    if (threadIdx.x < Gg) atomicAdd(&g_cnt[threadIdx.x], scn[threadIdx.x]);
}

// ---------------- head: mean-pool normalize + fc3(lrelu) + fc4 ----------------
__global__ void head_k(const float* __restrict__ fc3W, const float* __restrict__ fc3b,
                       const float* __restrict__ fc4W, const float* __restrict__ fc4b,
                       float* __restrict__ out)
{
    __shared__ float p[Gg * Hh];
    __shared__ float o1[Gg * 48];
    for (int i = threadIdx.x; i < Gg * Hh; i += blockDim.x) {
        int g = i / 96;
        p[i] = g_pooled[i] / fmaxf(g_cnt[g], 1.f);
    }
    __syncthreads();
    for (int i = threadIdx.x; i < Gg * 48; i += blockDim.x) {
        int g = i / 48, c = i % 48;
        float a = fc3b[c];
        for (int k = 0; k < 96; k++) a = fmaf(p[g * 96 + k], fc3W[k * 48 + c], a);
        o1[i] = lrelu01(a);
    }
    __syncthreads();
    for (int i = threadIdx.x; i < Gg * NCLS; i += blockDim.x) {
        int g = i / NCLS, c = i % NCLS;
        float a = fc4b[c];
        for (int k = 0; k < 48; k++) a = fmaf(o1[g * 48 + k], fc4W[k * NCLS + c], a);
        out[i] = a;
    }
}

// ---------------- launch ----------------
extern "C" void kernel_launch(void* const* d_in, const int* in_sizes, int n_in,
                              void* d_out, int out_size)
{
    const float* x     = (const float*)d_in[0];
    const int*   ei    = (const int*)d_in[1];
    const int*   batch = (const int*)d_in[2];
    const float* embW  = (const float*)d_in[3];
    const float* embB  = (const float*)d_in[4];
    const float* cW[3]  = {(const float*)d_in[5],  (const float*)d_in[9],  (const float*)d_in[13]};
    const float* cAS[3] = {(const float*)d_in[6],  (const float*)d_in[10], (const float*)d_in[14]};
    const float* cAD[3] = {(const float*)d_in[7],  (const float*)d_in[11], (const float*)d_in[15]};
    const float* cB[3]  = {(const float*)d_in[8],  (const float*)d_in[12], (const float*)d_in[16]};
    const float* fcW[2] = {(const float*)d_in[17], (const float*)d_in[19]};
    const float* fcB[2] = {(const float*)d_in[18], (const float*)d_in[20]};
    const float* bnG[3] = {(const float*)d_in[21], (const float*)d_in[23], (const float*)d_in[25]};
    const float* bnB[3] = {(const float*)d_in[22], (const float*)d_in[24], (const float*)d_in[26]};
    const float* fc3W = (const float*)d_in[27];
    const float* fc3b = (const float*)d_in[28];
    const float* fc4W = (const float*)d_in[29];
    const float* fc4b = (const float*)d_in[30];
    float* out = (float*)d_out;

    float *ph, *pid, *php, *ptmp, *pss, *psd;
    cudaGetSymbolAddress((void**)&ph,   g_h);
    cudaGetSymbolAddress((void**)&pid,  g_id);
    cudaGetSymbolAddress((void**)&php,  g_hp);
    cudaGetSymbolAddress((void**)&ptmp, g_tmp);
    cudaGetSymbolAddress((void**)&pss,  g_ss);
    cudaGetSymbolAddress((void**)&psd,  g_sd);

    const int EB = (ETOT + 255) / 256;
    const int GB = (Nn + 63) / 64;
    const int WB = (Nn * 32 + 255) / 256;

    zero_k<<<256, 256>>>();
    count_k<<<EB, 256>>>(ei);
    scan_k<<<1, 1024>>>();
    scatter_k<<<EB, 256>>>(ei);

    // embed: h = lrelu(x @ embW + embB); identity = h
    gemm96<1, true><<<GB, 384>>>(x, embW, embB, ph, pid, Nn, 256);

    for (int l = 0; l < 3; l++) {
        gemm96<0, false><<<GB, 384>>>(ph, cW[l], nullptr, php, nullptr, Nn, 96);
        scores_k<<<WB, 256>>>(php, cAS[l], cAD[l], pss, psd);
        agg_k<<<WB, 256>>>(php, pss, psd, cB[l], ptmp);
        zerobn_k<<<1, 96>>>();
        bnstats_k<<<1024, 96>>>(ptmp);
        bnapply_k<<<4096, 256>>>(ptmp, pid, bnG[l], bnB[l], ph);
        if (l < 2)
            gemm96<1, false><<<GB, 384>>>(ph, fcW[l], fcB[l], ph, nullptr, Nn, 96);
    }

    expool_k<<<160, 256>>>(ph, batch);
    head_k<<<1, 256>>>(fc3W, fc3b, fc4W, fc4b, out);
}

// round 3
// speedup vs baseline: 1.2807x; 1.2807x over previous
#include <cuda_runtime.h>
#include <math.h>

#define Nn 50000
#define Ee 800000
#define ETOT 850000
#define Hh 96
#define Gg 64
#define NCLS 4
#define BNEPS 1e-5f

// ---------------- device scratch (static, no allocs) ----------------
__device__ float g_h[Nn * Hh];      // current node features
__device__ float g_id[Nn * Hh];     // identity (residual)
__device__ float g_hp[Nn * Hh];     // h @ W (per GAT layer)
__device__ float g_tmp[Nn * Hh];    // GAT output before BN
__device__ float g_ss[Nn], g_sd[Nn];
__device__ float g_ew[ETOT];        // per-edge softmax numerators
__device__ int   g_deg[Nn];
__device__ int   g_rs[Nn + 1];
__device__ int   g_cur[Nn];
__device__ int   g_csr[ETOT];
__device__ float g_bnsum[3 * Hh], g_bnsq[3 * Hh];   // per-layer BN stat slots
__device__ float g_pooled[Gg * Hh];
__device__ float g_cnt[Gg];

__device__ __forceinline__ float lrelu01(float v) { return v >= 0.f ? v : 0.01f * v; }

// ---------------- zero / init (once per call) ----------------
__global__ void zero_k() {
    int i = blockIdx.x * blockDim.x + threadIdx.x;
    int stride = gridDim.x * blockDim.x;
    for (int j = i; j < Nn; j += stride) g_deg[j] = 0;
    if (i < Gg * Hh) g_pooled[i] = 0.f;
    if (i < Gg) g_cnt[i] = 0.f;
    if (i < 3 * Hh) { g_bnsum[i] = 0.f; g_bnsq[i] = 0.f; }
}

// ---------------- CSR build ----------------
__global__ void count_k(const int* __restrict__ ei) {
    int i = blockIdx.x * blockDim.x + threadIdx.x;
    if (i >= ETOT) return;
    int d = (i < Ee) ? ei[Ee + i] : (i - Ee);
    atomicAdd(&g_deg[d], 1);
}

__global__ void scan_k() {
    __shared__ int part[1024];
    int t = threadIdx.x;
    const int CH = (Nn + 1023) / 1024;   // 49
    int base = t * CH;
    int s = 0;
    for (int i = 0; i < CH; i++) {
        int idx = base + i;
        if (idx < Nn) s += g_deg[idx];
    }
    part[t] = s;
    __syncthreads();
    for (int off = 1; off < 1024; off <<= 1) {
        int v = (t >= off) ? part[t - off] : 0;
        __syncthreads();
        part[t] += v;
        __syncthreads();
    }
    int run = (t == 0) ? 0 : part[t - 1];
    for (int i = 0; i < CH; i++) {
        int idx = base + i;
        if (idx < Nn) {
            g_rs[idx] = run;
            g_cur[idx] = run;
            run += g_deg[idx];
        }
    }
    if (t == blockDim.x - 1) g_rs[Nn] = part[blockDim.x - 1];
}

__global__ void scatter_k(const int* __restrict__ ei) {
    int i = blockIdx.x * blockDim.x + threadIdx.x;
    if (i >= ETOT) return;
    int sN, dN;
    if (i < Ee) { sN = ei[i]; dN = ei[Ee + i]; }
    else        { sN = i - Ee; dN = i - Ee; }
    int pos = atomicAdd(&g_cur[dN], 1);
    g_csr[pos] = sN;
}

// ---------------- GEMM: C[M,96] = act(A'[M,K] @ W[K,96] + bias) ----------------
// tile 128 rows x 96 cols, 384 threads, micro-tile 8x4.
// MODE==1: A' = lrelu(sc[c]*A + sh[c]) + A2   (fused BatchNorm apply + residual, K must be 96)
template <int ACT, int MODE, int DUP>
__global__ __launch_bounds__(384, 2) void gemm128(
    const float* __restrict__ A, const float* __restrict__ A2,
    const float* __restrict__ gma, const float* __restrict__ bta,
    const float* __restrict__ sumP, const float* __restrict__ sqP,
    const float* __restrict__ W, const float* __restrict__ bias,
    float* __restrict__ C, float* __restrict__ C2, int M, int K)
{
    __shared__ float Ash[32][132];   // [k][m]
    __shared__ float Wsh[32][96];
    __shared__ float s_sc[96], s_sh[96];
    int tid = threadIdx.x;
    if (MODE == 1) {
        if (tid < 96) {
            float mu = sumP[tid] * (1.f / Nn);
            float var = sqP[tid] * (1.f / Nn) - mu * mu;
            float is = rsqrtf(var + BNEPS);
            float gv = gma[tid];
            s_sc[tid] = gv * is;
            s_sh[tid] = bta[tid] - mu * gv * is;
        }
        __syncthreads();
    }
    int cg = tid % 24;               // cols cg*4..+3
    int rg = tid / 24;               // rows rg*8..+7
    int rowBase = blockIdx.x * 128;
    float acc[8][4] = {};
    for (int kc = 0; kc < K; kc += 32) {
        // load A chunk (transposed) : 128 rows x 32 k = 1024 float4
        for (int idx = tid; idx < 1024; idx += 384) {
            int m = idx >> 3, kq = idx & 7;
            int r = rowBase + m;
            float4 v = make_float4(0.f, 0.f, 0.f, 0.f);
            if (r < M) {
                v = *(const float4*)&A[r * K + kc + kq * 4];
                if (MODE == 1) {
                    float4 u = *(const float4*)&A2[r * K + kc + kq * 4];
                    int c = kc + kq * 4;
                    v.x = lrelu01(fmaf(v.x, s_sc[c + 0], s_sh[c + 0])) + u.x;
                    v.y = lrelu01(fmaf(v.y, s_sc[c + 1], s_sh[c + 1])) + u.y;
                    v.z = lrelu01(fmaf(v.z, s_sc[c + 2], s_sh[c + 2])) + u.z;
                    v.w = lrelu01(fmaf(v.w, s_sc[c + 3], s_sh[c + 3])) + u.w;
                }
            }
            int k0 = kq * 4;
            Ash[k0 + 0][m] = v.x;
            Ash[k0 + 1][m] = v.y;
            Ash[k0 + 2][m] = v.z;
            Ash[k0 + 3][m] = v.w;
        }
        // load W chunk: 32 x 96 = 3072 floats
        #pragma unroll
        for (int j = 0; j < 8; j++) {
            int idx = tid + j * 384;
            int k = idx / 96, c = idx % 96;
            Wsh[k][c] = W[(kc + k) * 96 + c];
        }
        __syncthreads();
        #pragma unroll
        for (int k = 0; k < 32; k++) {
            float4 al = *(const float4*)&Ash[k][rg * 8];
            float4 ah = *(const float4*)&Ash[k][rg * 8 + 4];
            float4 w  = *(const float4*)&Wsh[k][cg * 4];
            float av[8] = {al.x, al.y, al.z, al.w, ah.x, ah.y, ah.z, ah.w};
            float wv[4] = {w.x, w.y, w.z, w.w};
            #pragma unroll
            for (int i = 0; i < 8; i++)
                #pragma unroll
                for (int j = 0; j < 4; j++)
                    acc[i][j] = fmaf(av[i], wv[j], acc[i][j]);
        }
        __syncthreads();
    }
    int c0 = cg * 4;
    float bv[4];
    #pragma unroll
    for (int j = 0; j < 4; j++) bv[j] = bias ? bias[c0 + j] : 0.f;
    int r0 = rowBase + rg * 8;
    #pragma unroll
    for (int i = 0; i < 8; i++) {
        int r = r0 + i;
        if (r < M) {
            float v0 = acc[i][0] + bv[0];
            float v1 = acc[i][1] + bv[1];
            float v2 = acc[i][2] + bv[2];
            float v3 = acc[i][3] + bv[3];
            if (ACT) { v0 = lrelu01(v0); v1 = lrelu01(v1); v2 = lrelu01(v2); v3 = lrelu01(v3); }
            float4 o = make_float4(v0, v1, v2, v3);
            *(float4*)&C[r * 96 + c0] = o;
            if (DUP) *(float4*)&C2[r * 96 + c0] = o;
        }
    }
}

// ---------------- per-node attention scores ----------------
__global__ void scores_k(const float* __restrict__ hp,
                         const float* __restrict__ as_, const float* __restrict__ ad_,
                         float* __restrict__ ss, float* __restrict__ sd)
{
    int w = (blockIdx.x * blockDim.x + threadIdx.x) >> 5;
    int lane = threadIdx.x & 31;
    if (w >= Nn) return;
    const float* row = hp + w * 96;
    float s1 = 0.f, s2 = 0.f;
    #pragma unroll
    for (int j = 0; j < 3; j++) {
        float v = row[lane + 32 * j];
        s1 = fmaf(v, as_[lane + 32 * j], s1);
        s2 = fmaf(v, ad_[lane + 32 * j], s2);
    }
    #pragma unroll
    for (int o = 16; o; o >>= 1) {
        s1 += __shfl_xor_sync(0xffffffffu, s1, o);
        s2 += __shfl_xor_sync(0xffffffffu, s2, o);
    }
    if (lane == 0) { ss[w] = s1; sd[w] = s2; }
}

// ---------------- GAT aggregation: warp per destination node ----------------
__global__ void agg_k(const float* __restrict__ hp,
                      const float* __restrict__ ss, const float* __restrict__ sd,
                      const float* __restrict__ bias, float* __restrict__ out)
{
    int d = (blockIdx.x * blockDim.x + threadIdx.x) >> 5;
    int lane = threadIdx.x & 31;
    if (d >= Nn) return;
    int s0 = g_rs[d], s1e = g_rs[d + 1];
    float sdd = sd[d];
    // pass 1: max
    float m = -3.4e38f;
    for (int j = s0 + lane; j < s1e; j += 32) {
        int s = g_csr[j];
        float e = ss[s] + sdd;
        e = (e >= 0.f) ? e : 0.2f * e;
        m = fmaxf(m, e);
    }
    #pragma unroll
    for (int o = 16; o; o >>= 1) m = fmaxf(m, __shfl_xor_sync(0xffffffffu, m, o));
    // pass 2: denominator + cache numerators
    float denom = 0.f;
    for (int j = s0 + lane; j < s1e; j += 32) {
        int s = g_csr[j];
        float e = ss[s] + sdd;
        e = (e >= 0.f) ? e : 0.2f * e;
        float wv = __expf(e - m);
        g_ew[j] = wv;
        denom += wv;
    }
    #pragma unroll
    for (int o = 16; o; o >>= 1) denom += __shfl_xor_sync(0xffffffffu, denom, o);
    float inv = 1.f / denom;
    // pass 3: weighted aggregation (all 32 lanes on features)
    float a0 = 0.f, a1 = 0.f, a2 = 0.f;
    for (int j = s0; j < s1e; j++) {
        int s = g_csr[j];                 // warp-uniform broadcast loads
        float wgt = g_ew[j] * inv;
        const float* row = hp + s * 96;
        a0 = fmaf(wgt, row[lane], a0);
        a1 = fmaf(wgt, row[lane + 32], a1);
        a2 = fmaf(wgt, row[lane + 64], a2);
    }
    out[d * 96 + lane]      = a0 + bias[lane];
    out[d * 96 + lane + 32] = a1 + bias[lane + 32];
    out[d * 96 + lane + 64] = a2 + bias[lane + 64];
}

// ---------------- BatchNorm statistics ----------------
__global__ void bnstats_k(const float* __restrict__ t,
                          float* __restrict__ sumP, float* __restrict__ sqP) {
    int c = threadIdx.x;   // 96 threads
    float s = 0.f, q = 0.f;
    for (int r = blockIdx.x; r < Nn; r += gridDim.x) {
        float v = t[r * 96 + c];
        s += v;
        q = fmaf(v, v, q);
    }
    atomicAdd(&sumP[c], s);
    atomicAdd(&sqP[c], q);
}

// ---------------- fused BN-apply + Poincare expmap0 + segment pooling ----------------
__global__ void expool_k(const float* __restrict__ t, const float* __restrict__ idn,
                         const float* __restrict__ gma, const float* __restrict__ bta,
                         const float* __restrict__ sumP, const float* __restrict__ sqP,
                         const int* __restrict__ batch)
{
    __shared__ float sp[Gg * Hh];
    __shared__ float scn[Gg];
    __shared__ float s_sc[96], s_sh[96];
    if (threadIdx.x < 96) {
        int c = threadIdx.x;
        float mu = sumP[c] * (1.f / Nn);
        float var = sqP[c] * (1.f / Nn) - mu * mu;
        float is = rsqrtf(var + BNEPS);
        float gv = gma[c];
        s_sc[c] = gv * is;
        s_sh[c] = bta[c] - mu * gv * is;
    }
    for (int i = threadIdx.x; i < Gg * Hh; i += blockDim.x) sp[i] = 0.f;
    if (threadIdx.x < Gg) scn[threadIdx.x] = 0.f;
    __syncthreads();
    int lane = threadIdx.x & 31;
    int warp = (blockIdx.x * blockDim.x + threadIdx.x) >> 5;
    int nwarps = (gridDim.x * blockDim.x) >> 5;
    for (int n = warp; n < Nn; n += nwarps) {
        float v0 = lrelu01(fmaf(t[n * 96 + lane],      s_sc[lane],      s_sh[lane]))      + idn[n * 96 + lane];
        float v1 = lrelu01(fmaf(t[n * 96 + lane + 32], s_sc[lane + 32], s_sh[lane + 32])) + idn[n * 96 + lane + 32];
        float v2 = lrelu01(fmaf(t[n * 96 + lane + 64], s_sc[lane + 64], s_sh[lane + 64])) + idn[n * 96 + lane + 64];
        float q = v0 * v0 + v1 * v1 + v2 * v2;
        #pragma unroll
        for (int o = 16; o; o >>= 1) q += __shfl_xor_sync(0xffffffffu, q, o);
        float nrm = fmaxf(sqrtf(q), 1e-15f);
        float s = tanhf(nrm) / nrm;
        int g = batch[n];
        atomicAdd(&sp[g * 96 + lane], v0 * s);
        atomicAdd(&sp[g * 96 + lane + 32], v1 * s);
        atomicAdd(&sp[g * 96 + lane + 64], v2 * s);
        if (lane == 0) atomicAdd(&scn[g], 1.f);
    }
    __syncthreads();
    for (int i = threadIdx.x; i < Gg * Hh; i += blockDim.x) atomicAdd(&g_pooled[i], sp[i]);
    if (threadIdx.x < Gg) atomicAdd(&g_cnt[threadIdx.x], scn[threadIdx.x]);
}

// ---------------- head ----------------
__global__ void head_k(const float* __restrict__ fc3W, const float* __restrict__ fc3b,
                       const float* __restrict__ fc4W, const float* __restrict__ fc4b,
                       float* __restrict__ out)
{
    __shared__ float p[Gg * Hh];
    __shared__ float o1[Gg * 48];
    for (int i = threadIdx.x; i < Gg * Hh; i += blockDim.x) {
        int g = i / 96;
        p[i] = g_pooled[i] / fmaxf(g_cnt[g], 1.f);
    }
    __syncthreads();
    for (int i = threadIdx.x; i < Gg * 48; i += blockDim.x) {
        int g = i / 48, c = i % 48;
        float a = fc3b[c];
        for (int k = 0; k < 96; k++) a = fmaf(p[g * 96 + k], fc3W[k * 48 + c], a);
        o1[i] = lrelu01(a);
    }
    __syncthreads();
    for (int i = threadIdx.x; i < Gg * NCLS; i += blockDim.x) {
        int g = i / NCLS, c = i % NCLS;
        float a = fc4b[c];
        for (int k = 0; k < 48; k++) a = fmaf(o1[g * 48 + k], fc4W[k * NCLS + c], a);
        out[i] = a;
    }
}

// ---------------- launch ----------------
extern "C" void kernel_launch(void* const* d_in, const int* in_sizes, int n_in,
                              void* d_out, int out_size)
{
    const float* x     = (const float*)d_in[0];
    const int*   ei    = (const int*)d_in[1];
    const int*   batch = (const int*)d_in[2];
    const float* embW  = (const float*)d_in[3];
    const float* embB  = (const float*)d_in[4];
    const float* cW[3]  = {(const float*)d_in[5],  (const float*)d_in[9],  (const float*)d_in[13]};
    const float* cAS[3] = {(const float*)d_in[6],  (const float*)d_in[10], (const float*)d_in[14]};
    const float* cAD[3] = {(const float*)d_in[7],  (const float*)d_in[11], (const float*)d_in[15]};
    const float* cB[3]  = {(const float*)d_in[8],  (const float*)d_in[12], (const float*)d_in[16]};
    const float* fcW[2] = {(const float*)d_in[17], (const float*)d_in[19]};
    const float* fcB[2] = {(const float*)d_in[18], (const float*)d_in[20]};
    const float* bnG[3] = {(const float*)d_in[21], (const float*)d_in[23], (const float*)d_in[25]};
    const float* bnB[3] = {(const float*)d_in[22], (const float*)d_in[24], (const float*)d_in[26]};
    const float* fc3W = (const float*)d_in[27];
    const float* fc3b = (const float*)d_in[28];
    const float* fc4W = (const float*)d_in[29];
    const float* fc4b = (const float*)d_in[30];
    float* out = (float*)d_out;

    float *ph, *pid, *php, *ptmp, *pss, *psd, *pbs, *pbq;
    cudaGetSymbolAddress((void**)&ph,   g_h);
    cudaGetSymbolAddress((void**)&pid,  g_id);
    cudaGetSymbolAddress((void**)&php,  g_hp);
    cudaGetSymbolAddress((void**)&ptmp, g_tmp);
    cudaGetSymbolAddress((void**)&pss,  g_ss);
    cudaGetSymbolAddress((void**)&psd,  g_sd);
    cudaGetSymbolAddress((void**)&pbs,  g_bnsum);
    cudaGetSymbolAddress((void**)&pbq,  g_bnsq);

    const int EB = (ETOT + 255) / 256;
    const int GB = (Nn + 127) / 128;
    const int WB = (Nn * 32 + 255) / 256;

    // Fork: CSR build runs concurrently with embed GEMM.
    // Streams/events are intentionally not destroyed (kernel_launch is called
    // only for correctness + capture; destroying a stream mid-capture aborts it).
    cudaStream_t s1;
    cudaStreamCreateWithFlags(&s1, cudaStreamNonBlocking);
    cudaEvent_t evFork, evJoin;
    cudaEventCreateWithFlags(&evFork, cudaEventDisableTiming);
    cudaEventCreateWithFlags(&evJoin, cudaEventDisableTiming);

    cudaEventRecord(evFork, 0);
    cudaStreamWaitEvent(s1, evFork, 0);
    zero_k<<<256, 256, 0, s1>>>();
    count_k<<<EB, 256, 0, s1>>>(ei);
    scan_k<<<1, 1024, 0, s1>>>();
    scatter_k<<<EB, 256, 0, s1>>>(ei);
    cudaEventRecord(evJoin, s1);

    // embed: h = lrelu(x @ embW + embB); identity = h   (on default stream)
    gemm128<1, 0, 1><<<GB, 384>>>(x, nullptr, nullptr, nullptr, nullptr, nullptr,
                                  embW, embB, ph, pid, Nn, 256);

    for (int l = 0; l < 3; l++) {
        gemm128<0, 0, 0><<<GB, 384>>>(ph, nullptr, nullptr, nullptr, nullptr, nullptr,
                                      cW[l], nullptr, php, nullptr, Nn, 96);
        scores_k<<<WB, 256>>>(php, cAS[l], cAD[l], pss, psd);
        if (l == 0) cudaStreamWaitEvent(0, evJoin, 0);   // CSR ready before first agg
        agg_k<<<WB, 256>>>(php, pss, psd, cB[l], ptmp);
        bnstats_k<<<1024, 96>>>(ptmp, pbs + l * Hh, pbq + l * Hh);
        if (l < 2) {
            // h = lrelu( (lrelu(bn(tmp)) + id) @ fcW + fcB )   — BN fused into A-load
            gemm128<1, 1, 0><<<GB, 384>>>(ptmp, pid, bnG[l], bnB[l], pbs + l * Hh, pbq + l * Hh,
                                          fcW[l], fcB[l], ph, nullptr, Nn, 96);
        }
    }

    expool_k<<<160, 256>>>(ptmp, pid, bnG[2], bnB[2], pbs + 2 * Hh, pbq + 2 * Hh, batch);
    head_k<<<1, 256>>>(fc3W, fc3b, fc4W, fc4b, out);
}